// round 2
// baseline (speedup 1.0000x reference)
#include <cuda_runtime.h>
#include <cuda_bf16.h>

// =============================================================
// NonLocalBlock: B=16, C=512, Ci=256, H=W=64, N=4096
//   proj  : [g;theta;phi] (768x512) @ x[b] (512x4096) -> proj[b] (768x4096)
//   f     : theta (256x4096) @ phi^T (4096x256) -> f[b] (256x256)  (split-K)
//   softmax rows of f
//   y     : f (256x256) @ g (256x4096) -> y[b] (256x4096)
//   z     : W_w (512x256) @ y (256x4096) + W_b -> z[b] (512x4096)
//   BN(train stats over B,H,W) * gamma + beta + x -> out
// =============================================================

#define BATCH 16
#define CCH   512
#define CI    256
#define NPIX  4096
#define SPLITK 8

// ---- scratch (device globals; no allocation allowed) ----
__device__ float d_proj[(size_t)BATCH * 768 * NPIX];          // 201 MB
__device__ float d_wstack[768 * CCH];                         // 1.5 MB
__device__ float d_bstack[768];
__device__ float d_fpart[(size_t)BATCH * SPLITK * CI * CI];   // 33.5 MB
__device__ float d_f[(size_t)BATCH * CI * CI];                // 4.2 MB
__device__ float d_y[(size_t)BATCH * CI * NPIX];              // 67 MB
__device__ float d_z[(size_t)BATCH * CCH * NPIX];             // 134 MB
__device__ float d_stats[2 * CCH];                            // mean | rstd

// =============================================================
// Generic NN SGEMM: C[b] = A[b] (MxK row-major) * B[b] (KxN row-major) + bias
// BM=128 BN=128 BK=8 TM=8 TN=8, 256 threads. M,N,K multiples of tile dims.
// =============================================================
__global__ __launch_bounds__(256) void sgemm_nn_128(
    const float* __restrict__ Ag, const float* __restrict__ Bg,
    float* __restrict__ Cg, const float* __restrict__ bias,
    int M, int N, int K,
    long long sA, long long sB, long long sC)
{
    const float* A = Ag + (long long)blockIdx.z * sA;
    const float* B = Bg + (long long)blockIdx.z * sB;
    float*       C = Cg + (long long)blockIdx.z * sC;

    const int rowStart = blockIdx.y * 128;
    const int colStart = blockIdx.x * 128;

    __shared__ float As[8][128];
    __shared__ float Bs[8][128];

    const int tid  = threadIdx.x;
    const int tRow = tid >> 4;          // 0..15
    const int tCol = tid & 15;          // 0..15

    // A loader: one float4 along K per thread. aRow 0..127, aK {0,4}
    const int aRow = tid >> 1;
    const int aK   = (tid & 1) * 4;
    // B loader: one float4 along N per thread. bRow 0..7, bCol 0..124
    const int bRow = tid >> 5;
    const int bCol = (tid & 31) * 4;

    float acc[8][8];
    #pragma unroll
    for (int i = 0; i < 8; i++)
        #pragma unroll
        for (int j = 0; j < 8; j++) acc[i][j] = 0.f;

    for (int k0 = 0; k0 < K; k0 += 8) {
        float4 av = *(const float4*)&A[(long long)(rowStart + aRow) * K + k0 + aK];
        As[aK + 0][aRow] = av.x;
        As[aK + 1][aRow] = av.y;
        As[aK + 2][aRow] = av.z;
        As[aK + 3][aRow] = av.w;
        float4 bv = *(const float4*)&B[(long long)(k0 + bRow) * N + colStart + bCol];
        *(float4*)&Bs[bRow][bCol] = bv;
        __syncthreads();

        #pragma unroll
        for (int k = 0; k < 8; k++) {
            float ra[8], rb[8];
            #pragma unroll
            for (int i = 0; i < 8; i++) ra[i] = As[k][tRow * 8 + i];
            #pragma unroll
            for (int j = 0; j < 8; j++) rb[j] = Bs[k][tCol * 8 + j];
            #pragma unroll
            for (int i = 0; i < 8; i++)
                #pragma unroll
                for (int j = 0; j < 8; j++) acc[i][j] += ra[i] * rb[j];
        }
        __syncthreads();
    }

    #pragma unroll
    for (int i = 0; i < 8; i++) {
        const int gr = rowStart + tRow * 8 + i;
        const float bvv = bias ? bias[gr] : 0.f;
        float* cp = C + (long long)gr * N + colStart + tCol * 8;
        #pragma unroll
        for (int j = 0; j < 8; j++) cp[j] = acc[i][j] + bvv;
    }
}

// =============================================================
// NT split-K GEMM for f = theta @ phi^T.
// A = theta base (per-batch stride 768*NPIX applied here), ld=4096
// B = phi base, ld=4096.  M=N=256, K=4096 split into SPLITK chunks.
// Output partials: fpart[p][256][256], p = b*SPLITK + s.
// 64x64 tile, BK=16, 256 threads, 4x4 per thread.
// =============================================================
__global__ __launch_bounds__(256) void sgemm_nt_splitk(
    const float* __restrict__ thetaBase, const float* __restrict__ phiBase,
    float* __restrict__ fpart)
{
    const int p = blockIdx.z;
    const int b = p / SPLITK;
    const int s = p % SPLITK;
    const int Kc = NPIX / SPLITK;           // 512
    const int kStart = s * Kc;

    const float* A = thetaBase + (long long)b * (768LL * NPIX);
    const float* B = phiBase   + (long long)b * (768LL * NPIX);

    const int rowStart = blockIdx.y * 64;
    const int colStart = blockIdx.x * 64;

    __shared__ float As[16][64];
    __shared__ float Bs[16][64];

    const int tid  = threadIdx.x;
    const int tRow = tid >> 4;
    const int tCol = tid & 15;
    const int lRow = tid >> 2;              // 0..63
    const int lK   = (tid & 3) * 4;         // 0,4,8,12

    float acc[4][4];
    #pragma unroll
    for (int i = 0; i < 4; i++)
        #pragma unroll
        for (int j = 0; j < 4; j++) acc[i][j] = 0.f;

    for (int k0 = kStart; k0 < kStart + Kc; k0 += 16) {
        float4 av = *(const float4*)&A[(long long)(rowStart + lRow) * NPIX + k0 + lK];
        As[lK + 0][lRow] = av.x;
        As[lK + 1][lRow] = av.y;
        As[lK + 2][lRow] = av.z;
        As[lK + 3][lRow] = av.w;
        float4 bv = *(const float4*)&B[(long long)(colStart + lRow) * NPIX + k0 + lK];
        Bs[lK + 0][lRow] = bv.x;
        Bs[lK + 1][lRow] = bv.y;
        Bs[lK + 2][lRow] = bv.z;
        Bs[lK + 3][lRow] = bv.w;
        __syncthreads();

        #pragma unroll
        for (int k = 0; k < 16; k++) {
            float ra[4], rb[4];
            #pragma unroll
            for (int i = 0; i < 4; i++) ra[i] = As[k][tRow * 4 + i];
            #pragma unroll
            for (int j = 0; j < 4; j++) rb[j] = Bs[k][tCol * 4 + j];
            #pragma unroll
            for (int i = 0; i < 4; i++)
                #pragma unroll
                for (int j = 0; j < 4; j++) acc[i][j] += ra[i] * rb[j];
        }
        __syncthreads();
    }

    float* Cp = fpart + (long long)p * (CI * CI);
    #pragma unroll
    for (int i = 0; i < 4; i++) {
        float* cp = Cp + (rowStart + tRow * 4 + i) * CI + colStart + tCol * 4;
        #pragma unroll
        for (int j = 0; j < 4; j++) cp[j] = acc[i][j];
    }
}

// =============================================================
// Softmax over rows of f (sums split-K partials first).
// One block (256 threads) per row; row = b*256 + c; element d = tid.
// =============================================================
__global__ __launch_bounds__(256) void softmax_rows(
    const float* __restrict__ fpart, float* __restrict__ f)
{
    const int row = blockIdx.x;             // 0..4095
    const int b = row >> 8;
    const int c = row & 255;
    const int d = threadIdx.x;

    float v = 0.f;
    #pragma unroll
    for (int s = 0; s < SPLITK; s++)
        v += fpart[((long long)(b * SPLITK + s)) * (CI * CI) + c * CI + d];

    __shared__ float red[256];
    red[d] = v;
    __syncthreads();
    for (int off = 128; off > 0; off >>= 1) {
        if (d < off) red[d] = fmaxf(red[d], red[d + off]);
        __syncthreads();
    }
    const float m = red[0];
    __syncthreads();
    const float e = __expf(v - m);
    red[d] = e;
    __syncthreads();
    for (int off = 128; off > 0; off >>= 1) {
        if (d < off) red[d] += red[d + off];
        __syncthreads();
    }
    f[(long long)row * CI + d] = e / red[0];
}

// =============================================================
// Per-channel BN stats over (B, N): one block per channel.
// =============================================================
__global__ __launch_bounds__(256) void bn_stats(
    const float* __restrict__ z, float* __restrict__ stats)
{
    const int c = blockIdx.x;
    const int t = threadIdx.x;
    float s = 0.f, sq = 0.f;
    for (int b = 0; b < BATCH; b++) {
        const float* p = z + ((long long)b * CCH + c) * NPIX;
        for (int n = t; n < NPIX; n += 256) {
            const float v = p[n];
            s  += v;
            sq += v * v;
        }
    }
    __shared__ float rs[256], rq[256];
    rs[t] = s; rq[t] = sq;
    __syncthreads();
    for (int off = 128; off > 0; off >>= 1) {
        if (t < off) { rs[t] += rs[t + off]; rq[t] += rq[t + off]; }
        __syncthreads();
    }
    if (t == 0) {
        const float cnt = (float)(BATCH * NPIX);
        const float m = rs[0] / cnt;
        const float var = rq[0] / cnt - m * m;
        stats[c]       = m;
        stats[CCH + c] = rsqrtf(var + 1e-5f);
    }
}

// =============================================================
// out = (z - mean)*rstd*gamma + beta + x   (float4 vectorized)
// =============================================================
__global__ __launch_bounds__(256) void bn_residual(
    const float* __restrict__ z, const float* __restrict__ x,
    const float* __restrict__ gamma, const float* __restrict__ beta,
    const float* __restrict__ stats, float* __restrict__ out)
{
    const long long i = (long long)blockIdx.x * blockDim.x + threadIdx.x; // float4 idx
    const int c = (int)((i >> 10) & (CCH - 1));   // (i*4 / 4096) % 512
    const float m  = stats[c];
    const float r  = stats[CCH + c];
    const float g  = gamma[c];
    const float bb = beta[c];
    const float4 zv = ((const float4*)z)[i];
    const float4 xv = ((const float4*)x)[i];
    float4 o;
    o.x = (zv.x - m) * r * g + bb + xv.x;
    o.y = (zv.y - m) * r * g + bb + xv.y;
    o.z = (zv.z - m) * r * g + bb + xv.z;
    o.w = (zv.w - m) * r * g + bb + xv.w;
    ((float4*)out)[i] = o;
}

// =============================================================
// Launch
// =============================================================
extern "C" void kernel_launch(void* const* d_in, const int* in_sizes, int n_in,
                              void* d_out, int out_size)
{
    (void)in_sizes; (void)n_in; (void)out_size;
    const float* x     = (const float*)d_in[0];
    const float* g_w   = (const float*)d_in[1];
    const float* g_b   = (const float*)d_in[2];
    const float* th_w  = (const float*)d_in[3];
    const float* th_b  = (const float*)d_in[4];
    const float* ph_w  = (const float*)d_in[5];
    const float* ph_b  = (const float*)d_in[6];
    const float* W_w   = (const float*)d_in[7];
    const float* W_b   = (const float*)d_in[8];
    const float* gamma = (const float*)d_in[9];
    const float* beta  = (const float*)d_in[10];
    float* out = (float*)d_out;

    float *proj, *wstack, *bstack, *fpart, *f, *y, *z, *stats;
    cudaGetSymbolAddress((void**)&proj,   d_proj);
    cudaGetSymbolAddress((void**)&wstack, d_wstack);
    cudaGetSymbolAddress((void**)&bstack, d_bstack);
    cudaGetSymbolAddress((void**)&fpart,  d_fpart);
    cudaGetSymbolAddress((void**)&f,      d_f);
    cudaGetSymbolAddress((void**)&y,      d_y);
    cudaGetSymbolAddress((void**)&z,      d_z);
    cudaGetSymbolAddress((void**)&stats,  d_stats);

    // stack weights [g; theta; phi] and biases (capturable D2D copies)
    cudaMemcpyAsync(wstack,              g_w,  (size_t)CI * CCH * 4, cudaMemcpyDeviceToDevice);
    cudaMemcpyAsync(wstack + 1 * CI*CCH, th_w, (size_t)CI * CCH * 4, cudaMemcpyDeviceToDevice);
    cudaMemcpyAsync(wstack + 2 * CI*CCH, ph_w, (size_t)CI * CCH * 4, cudaMemcpyDeviceToDevice);
    cudaMemcpyAsync(bstack,          g_b,  CI * 4, cudaMemcpyDeviceToDevice);
    cudaMemcpyAsync(bstack + CI,     th_b, CI * 4, cudaMemcpyDeviceToDevice);
    cudaMemcpyAsync(bstack + 2 * CI, ph_b, CI * 4, cudaMemcpyDeviceToDevice);

    const long long xStride    = (long long)CCH * NPIX;     // 2097152
    const long long projStride = 768LL * NPIX;              // 3145728
    const long long yStride    = (long long)CI * NPIX;      // 1048576
    const long long zStride    = (long long)CCH * NPIX;     // 2097152

    // 1) fused projections: proj[b] = wstack @ x[b] + bstack
    sgemm_nn_128<<<dim3(NPIX / 128, 768 / 128, BATCH), 256>>>(
        wstack, x, proj, bstack, 768, NPIX, CCH, 0, xStride, projStride);

    // 2) f partials = theta @ phi^T (split-K)
    sgemm_nt_splitk<<<dim3(CI / 64, CI / 64, BATCH * SPLITK), 256>>>(
        proj + (long long)CI * NPIX,       // theta rows 256..511
        proj + 2LL * CI * NPIX,            // phi rows 512..767
        fpart);

    // 3) softmax over rows
    softmax_rows<<<BATCH * CI, 256>>>(fpart, f);

    // 4) y[b] = f[b] @ g[b]
    sgemm_nn_128<<<dim3(NPIX / 128, CI / 128, BATCH), 256>>>(
        f, proj, y, nullptr, CI, NPIX, CI,
        (long long)CI * CI, projStride, yStride);

    // 5) z[b] = W_w @ y[b] + W_b
    sgemm_nn_128<<<dim3(NPIX / 128, CCH / 128, BATCH), 256>>>(
        W_w, y, z, W_b, CCH, NPIX, CI, 0, yStride, zStride);

    // 6) BN stats
    bn_stats<<<CCH, 256>>>(z, stats);

    // 7) BN + residual
    const long long total4 = (long long)BATCH * CCH * NPIX / 4;   // 8388608
    bn_residual<<<(unsigned)(total4 / 256), 256>>>(z, x, gamma, beta, stats, out);
}